// round 16
// baseline (speedup 1.0000x reference)
#include <cuda_runtime.h>
#include <cstdint>

#define NTHREADS 256
#define NWARPS   (NTHREADS / 32)
#define MAXB     4096

// Global scratch (device globals: allocation-free, graph-safe, self-resetting).
__device__ float    g_R[MAXB * 26];   // per-row 26 partial sums
__device__ unsigned g_rcnt[MAXB];     // per-row completed units
__device__ float    g_L[MAXB];        // per-row loss
__device__ unsigned g_done = 0;       // rows completed

__device__ __forceinline__ float ex2f_(float a) {
    float r; asm("ex2.approx.ftz.f32 %0, %1;" : "=f"(r) : "f"(a)); return r;
}
__device__ __forceinline__ float lg_(float a) {  // natural log
    float r; asm("lg2.approx.ftz.f32 %0, %1;" : "=f"(r) : "f"(a));
    return r * 0.6931471805599453f;
}
__device__ __forceinline__ void redadd_(float* p, float v) {
    asm volatile("red.global.add.f32 [%0], %1;" :: "l"(p), "f"(v) : "memory");
}
__device__ __forceinline__ float ldcg_(const float* p) {
    float r; asm volatile("ld.global.cg.f32 %0, [%1];" : "=f"(r) : "l"(p)); return r;
}
__device__ __forceinline__ void stcg_(float* p, float v) {
    asm volatile("st.global.cg.f32 [%0], %1;" :: "l"(p), "f"(v) : "memory");
}
__device__ __forceinline__ void pfl2_(const void* p) {
    asm volatile("prefetch.global.L2 [%0];" :: "l"(p));
}

__global__ __launch_bounds__(NTHREADS, 4)
void aed_persist_kernel(const float* __restrict__ o0, const float* __restrict__ o1,
                        const float* __restrict__ o2, const float* __restrict__ o3,
                        const void* __restrict__ targets,
                        float* __restrict__ out, int C, int B, int UPC)
{
    __shared__ float sred[NWARPS][26];
    __shared__ float sf[NTHREADS];
    __shared__ int   s_is64, s_fin, s_last;

    const int tid = threadIdx.x;
    const int C4  = C >> 2;
    const int IPR = (C4 + NTHREADS - 1) / NTHREADS;   // units per row (32)
    const int UNITS = B * IPR;

    // ---- targets-dtype detect once per CTA ----
    if (tid < 32) {
        const int* t32 = (const int*)targets;
        int n = B < 128 ? B : 128;
        bool ok = true;
        for (int i = tid; i < n; i += 32) ok &= (t32[2 * i + 1] == 0);
        unsigned msk = __ballot_sync(0xffffffffu, ok);
        if (tid == 0) s_is64 = (msk == 0xffffffffu);
    }
    __syncthreads();

    const float K    = 0.48089834696298783f;                 // log2(e)/3
    const float KS02 = 0.25f * 0.2f * 0.48089834696298783f;  // applied to raw sum

    // acc[0..3]=z1, [4..7]=zs, [8..11]=zt, [12..15]=wt, [16..25]=D
    float acc[26];
#pragma unroll
    for (int k = 0; k < 26; k++) acc[k] = 0.f;

    int u    = blockIdx.x * UPC;
    int uend = u + UPC; if (uend > UNITS) uend = UNITS;

    while (u < uend) {
        const int row     = u / IPR;
        int       rowEndU = (row + 1) * IPR; if (rowEndU > uend) rowEndU = uend;
        const int cnt     = rowEndU - u;
        int       k       = u - row * IPR;

        const size_t rb = (size_t)row * C4;
        const float4* p0 = (const float4*)o0 + rb;
        const float4* p1 = (const float4*)o1 + rb;
        const float4* p2 = (const float4*)o2 + rb;
        const float4* p3 = (const float4*)o3 + rb;
        float* mout = out + 1 + (size_t)row * C;  // 4-byte aligned only

        // unit k is full iff (k+1)*NTHREADS <= C4
        const int kFullEnd_row = C4 / NTHREADS;   // 31 when C4=8000
        int kStop = k + cnt;                      // one past last unit
        int kFull = (kStop < kFullEnd_row) ? kStop : kFullEnd_row;

        // NOTE: internal index is i_ (NOT i) so argument expressions can
        // safely reference outer variables without self-shadowing.
#define BODY(IDX)                                                          \
        do {                                                               \
            const int i_ = (IDX);                                          \
            float4 a  = __ldcs(p0 + i_);                                   \
            float4 bq = __ldcs(p1 + i_);                                   \
            float4 cq = __ldcs(p2 + i_);                                   \
            float4 dq = __ldcs(p3 + i_);                                   \
            pfl2_(p0 + i_ + 2 * NTHREADS);                                 \
            pfl2_(p1 + i_ + 2 * NTHREADS);                                 \
            pfl2_(p2 + i_ + 2 * NTHREADS);                                 \
            pfl2_(p3 + i_ + 2 * NTHREADS);                                 \
            float x0v[4] = {a.x,  a.y,  a.z,  a.w};                        \
            float x1v[4] = {bq.x, bq.y, bq.z, bq.w};                       \
            float x2v[4] = {cq.x, cq.y, cq.z, cq.w};                       \
            float x3v[4] = {dq.x, dq.y, dq.z, dq.w};                       \
            float mv[4];                                                   \
            _Pragma("unroll")                                              \
            for (int v = 0; v < 4; v++) {                                  \
                float x0 = x0v[v], x1 = x1v[v], x2 = x2v[v], x3 = x3v[v];  \
                float sum = (x0 + x1) + (x2 + x3);                         \
                float m = 0.25f * sum;                                     \
                mv[v] = m;                                                 \
                float km02 = sum * KS02;                                   \
                acc[16] = fmaf(x0, x0, acc[16]);                           \
                acc[17] = fmaf(x0, x1, acc[17]);                           \
                acc[18] = fmaf(x0, x2, acc[18]);                           \
                acc[19] = fmaf(x0, x3, acc[19]);                           \
                acc[20] = fmaf(x1, x1, acc[20]);                           \
                acc[21] = fmaf(x1, x2, acc[21]);                           \
                acc[22] = fmaf(x1, x3, acc[22]);                           \
                acc[23] = fmaf(x2, x2, acc[23]);                           \
                acc[24] = fmaf(x2, x3, acc[24]);                           \
                acc[25] = fmaf(x3, x3, acc[25]);                           \
                float xj[4] = {x0, x1, x2, x3};                            \
                _Pragma("unroll")                                          \
                for (int j = 0; j < 4; j++) {                              \
                    float x    = xj[j];                                    \
                    float arg3 = x * K;                                    \
                    float argT = fmaf(0.8f, arg3, km02);                   \
                    float e  = ex2f_(arg3);                                \
                    float et = ex2f_(argT);                                \
                    float e2 = e * e;                                      \
                    acc[j]      = fmaf(e2, e, acc[j]);                     \
                    acc[4 + j]  += e;                                      \
                    acc[8 + j]  += et;                                     \
                    acc[12 + j] = fmaf(et, m - x, acc[12 + j]);            \
                }                                                          \
            }                                                              \
            const int cbase = i_ << 2;                                     \
            __stcs(mout + cbase + 0, mv[0]);                               \
            __stcs(mout + cbase + 1, mv[1]);                               \
            __stcs(mout + cbase + 2, mv[2]);                               \
            __stcs(mout + cbase + 3, mv[3]);                               \
        } while (0)

        // full units: no bounds check in the hot loop
        for (; k < kFull; k++)
            BODY(k * NTHREADS + tid);
        // tail unit(s): guarded
        for (; k < kStop; k++) {
            const int idx = k * NTHREADS + tid;
            if (idx < C4) BODY(idx);
        }
#undef BODY
        u = rowEndU;

        // ---------- flush this row's partials ----------
        float r[26];
#pragma unroll
        for (int q = 0; q < 26; q++) { r[q] = acc[q]; acc[q] = 0.f; }

        const unsigned FULL = 0xffffffffu;
#pragma unroll
        for (int off = 16; off > 0; off >>= 1)
#pragma unroll
            for (int q = 0; q < 26; q++)
                r[q] += __shfl_down_sync(FULL, r[q], off);

        const int lane = tid & 31, wid = tid >> 5;
        if (lane == 0)
#pragma unroll
            for (int q = 0; q < 26; q++) sred[wid][q] = r[q];
        __syncthreads();

        if (tid == 0) {
            for (int w = 1; w < NWARPS; w++)
#pragma unroll
                for (int q = 0; q < 26; q++) r[q] += sred[w][q];
            float* rowR = g_R + row * 26;
#pragma unroll
            for (int q = 0; q < 26; q++) redadd_(rowR + q, r[q]);
            __threadfence();
            unsigned v = atomicAdd(&g_rcnt[row], (unsigned)cnt);
            s_fin  = (v + (unsigned)cnt == (unsigned)IPR);
            s_last = 0;
        }
        __syncthreads();

        if (s_fin) {
            if (tid == 0) {
                __threadfence();  // acquire all red.adds for this row
                float* rowR = g_R + row * 26;
                float rr[26];
#pragma unroll
                for (int q = 0; q < 26; q++) { rr[q] = ldcg_(rowR + q); stcg_(rowR + q, 0.f); }
                g_rcnt[row] = 0;  // reset for next replay

                const int* t32 = (const int*)targets;
                int tgti = s_is64 ? (int)(((const long long*)targets)[row]) : t32[row];
                size_t off = (size_t)row * C + tgti;
                float xt[4] = {__ldg(o0 + off), __ldg(o1 + off),
                               __ldg(o2 + off), __ldg(o3 + off)};

                const float invC = 1.0f / (float)C;
                float CE[4], KD[4];
#pragma unroll
                for (int j = 0; j < 4; j++) {
                    float lse1 = lg_(rr[j]);           // logsumexp(x),   M=0
                    float lses = lg_(rr[4 + j]);       // logsumexp(x/T)
                    float lset = lg_(rr[8 + j]);       // logsumexp(t/T)
                    CE[j] = lse1 - xt[j];
                    float S = rr[12 + j] / rr[8 + j];  // sum_c p_t*(m-x)
                    KD[j] = 9.0f * invC * ((0.2f / 3.f) * S + lses - lset);
                }

                float dd[10];
                int idx = 0;
#pragma unroll
                for (int j = 0; j < 4; j++)
#pragma unroll
                    for (int q = j; q < 4; q++) { dd[idx] = rr[16 + idx] - xt[j] * xt[q]; idx++; }
                float n0 = sqrtf(dd[0]), n1 = sqrtf(dd[4]), n2 = sqrtf(dd[7]), n3 = sqrtf(dd[9]);
                float dal = dd[1] / (n0 * n1) + dd[2] / (n0 * n2) + dd[3] / (n0 * n3)
                          + dd[5] / (n1 * n2) + dd[6] / (n1 * n3) + dd[8] / (n2 * n3);

                float irm = 0.f, mn = 3.402823466e38f;
#pragma unroll
                for (int j = 0; j < 4; j++) { irm += CE[j] + KD[j]; mn = fminf(mn, CE[j]); }
                stcg_(&g_L[row], irm + 0.7f * mn + 0.3f * dal);

                __threadfence();
                unsigned vd = atomicAdd(&g_done, 1u);
                s_last = (vd == (unsigned)(B - 1));
            }
            __syncthreads();

            if (s_last) {
                __threadfence();
                float a2 = 0.f;
                for (int i2 = tid; i2 < B; i2 += NTHREADS) a2 += ldcg_(&g_L[i2]);
                sf[tid] = a2;
                __syncthreads();
                for (int st = NTHREADS / 2; st > 0; st >>= 1) {
                    if (tid < st) sf[tid] += sf[tid + st];
                    __syncthreads();
                }
                if (tid == 0) {
                    out[0] = sf[0] / (float)B;
                    g_done = 0;  // reset for next replay
                }
            }
        }
    }
}

extern "C" void kernel_launch(void* const* d_in, const int* in_sizes, int n_in,
                              void* d_out, int out_size) {
    const float* o0 = (const float*)d_in[0];
    const float* o1 = (const float*)d_in[1];
    const float* o2 = (const float*)d_in[2];
    const float* o3 = (const float*)d_in[3];
    const void*  tg = d_in[4];
    const int B = in_sizes[4];
    const int C = in_sizes[0] / B;
    float* out = (float*)d_out;

    int dev = 0, nsm = 148;
    cudaGetDevice(&dev);
    cudaDeviceGetAttribute(&nsm, cudaDevAttrMultiProcessorCount, dev);

    const int C4    = C >> 2;
    const int IPR   = (C4 + NTHREADS - 1) / NTHREADS;
    const int UNITS = B * IPR;
    int grid = nsm * 4;
    if (grid > UNITS) grid = UNITS;
    const int UPC = (UNITS + grid - 1) / grid;

    aed_persist_kernel<<<grid, NTHREADS>>>(o0, o1, o2, o3, tg, out, C, B, UPC);
}

// round 17
// speedup vs baseline: 1.4055x; 1.4055x over previous
#include <cuda_runtime.h>
#include <cstdint>

#define NTHREADS 256
#define NWARPS   (NTHREADS / 32)
#define MAXB     4096

// Global scratch (device globals: allocation-free, graph-safe, self-resetting).
__device__ float    g_R[MAXB * 26];   // per-row 26 partial sums
__device__ unsigned g_rcnt[MAXB];     // per-row completed units
__device__ float    g_L[MAXB];        // per-row loss
__device__ unsigned g_done = 0;       // rows completed

__device__ __forceinline__ float ex2f_(float a) {
    float r; asm("ex2.approx.ftz.f32 %0, %1;" : "=f"(r) : "f"(a)); return r;
}
__device__ __forceinline__ float lg_(float a) {  // natural log
    float r; asm("lg2.approx.ftz.f32 %0, %1;" : "=f"(r) : "f"(a));
    return r * 0.6931471805599453f;
}
__device__ __forceinline__ void redadd_(float* p, float v) {
    asm volatile("red.global.add.f32 [%0], %1;" :: "l"(p), "f"(v) : "memory");
}
__device__ __forceinline__ float ldcg_(const float* p) {
    float r; asm volatile("ld.global.cg.f32 %0, [%1];" : "=f"(r) : "l"(p)); return r;
}
__device__ __forceinline__ void stcg_(float* p, float v) {
    asm volatile("st.global.cg.f32 [%0], %1;" :: "l"(p), "f"(v) : "memory");
}
__device__ __forceinline__ void pfl2_(const void* p) {
    asm volatile("prefetch.global.L2 [%0];" :: "l"(p));
}

__global__ __launch_bounds__(NTHREADS, 4)
void aed_persist_kernel(const float* __restrict__ o0, const float* __restrict__ o1,
                        const float* __restrict__ o2, const float* __restrict__ o3,
                        const void* __restrict__ targets,
                        float* __restrict__ out, int C, int B, int UPC)
{
    __shared__ float sred[NWARPS][26];
    __shared__ float sf[NTHREADS];
    __shared__ int   s_is64, s_fin, s_last;

    const int tid = threadIdx.x;
    const int C4  = C >> 2;
    const int IPR = (C4 + NTHREADS - 1) / NTHREADS;   // units per row (32)
    const int UNITS = B * IPR;

    // ---- targets-dtype detect once per CTA ----
    if (tid < 32) {
        const int* t32 = (const int*)targets;
        int n = B < 128 ? B : 128;
        bool ok = true;
        for (int i = tid; i < n; i += 32) ok &= (t32[2 * i + 1] == 0);
        unsigned msk = __ballot_sync(0xffffffffu, ok);
        if (tid == 0) s_is64 = (msk == 0xffffffffu);
    }
    __syncthreads();

    const float K    = 0.48089834696298783f;                 // log2(e)/3
    const float KS02 = 0.25f * 0.2f * 0.48089834696298783f;  // applied to raw sum

    // acc[0..3]=z1, [4..7]=zs, [8..11]=zt, [12..15]=wt, [16..25]=D
    float acc[26];
#pragma unroll
    for (int k = 0; k < 26; k++) acc[k] = 0.f;

    int u    = blockIdx.x * UPC;
    int uend = u + UPC; if (uend > UNITS) uend = UNITS;

    while (u < uend) {
        const int row     = u / IPR;
        int       rowEndU = (row + 1) * IPR; if (rowEndU > uend) rowEndU = uend;
        const int cnt     = rowEndU - u;
        int       k       = u - row * IPR;

        const size_t rb = (size_t)row * C4;
        const float4* p0 = (const float4*)o0 + rb;
        const float4* p1 = (const float4*)o1 + rb;
        const float4* p2 = (const float4*)o2 + rb;
        const float4* p3 = (const float4*)o3 + rb;
        float* mout = out + 1 + (size_t)row * C;  // 4-byte aligned only

        for (; u < rowEndU; u++, k++) {
            const int i = k * NTHREADS + tid;
            if (i < C4) {
                float4 a  = __ldcs(p0 + i);
                float4 bq = __ldcs(p1 + i);
                float4 cq = __ldcs(p2 + i);
                float4 dq = __ldcs(p3 + i);

                // L2 prefetch of next stage (same reg + 4096B imm; non-faulting)
                pfl2_(p0 + i + NTHREADS);
                pfl2_(p1 + i + NTHREADS);
                pfl2_(p2 + i + NTHREADS);
                pfl2_(p3 + i + NTHREADS);

                float x0v[4] = {a.x,  a.y,  a.z,  a.w};
                float x1v[4] = {bq.x, bq.y, bq.z, bq.w};
                float x2v[4] = {cq.x, cq.y, cq.z, cq.w};
                float x3v[4] = {dq.x, dq.y, dq.z, dq.w};
                float mv[4];

#pragma unroll
                for (int v = 0; v < 4; v++) {
                    float x0 = x0v[v], x1 = x1v[v], x2 = x2v[v], x3 = x3v[v];
                    float sum = (x0 + x1) + (x2 + x3);
                    float m = 0.25f * sum;
                    mv[v] = m;
                    float km02 = sum * KS02;   // = 0.2*K*m

                    acc[16] = fmaf(x0, x0, acc[16]);
                    acc[17] = fmaf(x0, x1, acc[17]);
                    acc[18] = fmaf(x0, x2, acc[18]);
                    acc[19] = fmaf(x0, x3, acc[19]);
                    acc[20] = fmaf(x1, x1, acc[20]);
                    acc[21] = fmaf(x1, x2, acc[21]);
                    acc[22] = fmaf(x1, x3, acc[22]);
                    acc[23] = fmaf(x2, x2, acc[23]);
                    acc[24] = fmaf(x2, x3, acc[24]);
                    acc[25] = fmaf(x3, x3, acc[25]);

                    float xj[4] = {x0, x1, x2, x3};
#pragma unroll
                    for (int j = 0; j < 4; j++) {
                        float x    = xj[j];
                        float arg3 = x * K;                   // x/3 * log2e
                        float argT = fmaf(0.8f, arg3, km02);  // t/3 * log2e
                        float e  = ex2f_(arg3);               // exp(x/3)
                        float et = ex2f_(argT);               // exp(t/3)
                        float e2 = e * e;
                        acc[j]      = fmaf(e2, e, acc[j]);    // exp(x) via cube
                        acc[4 + j]  += e;
                        acc[8 + j]  += et;
                        acc[12 + j] = fmaf(et, m - x, acc[12 + j]);
                    }
                }

                const int cbase = i << 2;
                __stcs(mout + cbase + 0, mv[0]);
                __stcs(mout + cbase + 1, mv[1]);
                __stcs(mout + cbase + 2, mv[2]);
                __stcs(mout + cbase + 3, mv[3]);
            }
        }

        // ---------- flush this row's partials ----------
        float r[26];
#pragma unroll
        for (int q = 0; q < 26; q++) { r[q] = acc[q]; acc[q] = 0.f; }

        const unsigned FULL = 0xffffffffu;
#pragma unroll
        for (int off = 16; off > 0; off >>= 1)
#pragma unroll
            for (int q = 0; q < 26; q++)
                r[q] += __shfl_down_sync(FULL, r[q], off);

        const int lane = tid & 31, wid = tid >> 5;
        if (lane == 0)
#pragma unroll
            for (int q = 0; q < 26; q++) sred[wid][q] = r[q];
        __syncthreads();

        if (tid == 0) {
            for (int w = 1; w < NWARPS; w++)
#pragma unroll
                for (int q = 0; q < 26; q++) r[q] += sred[w][q];
            float* rowR = g_R + row * 26;
#pragma unroll
            for (int q = 0; q < 26; q++) redadd_(rowR + q, r[q]);
            __threadfence();
            unsigned v = atomicAdd(&g_rcnt[row], (unsigned)cnt);
            s_fin  = (v + (unsigned)cnt == (unsigned)IPR);
            s_last = 0;
        }
        __syncthreads();

        if (s_fin) {
            if (tid == 0) {
                __threadfence();  // acquire all red.adds for this row
                float* rowR = g_R + row * 26;
                float rr[26];
#pragma unroll
                for (int q = 0; q < 26; q++) { rr[q] = ldcg_(rowR + q); stcg_(rowR + q, 0.f); }
                g_rcnt[row] = 0;  // reset for next replay

                const int* t32 = (const int*)targets;
                int tgti = s_is64 ? (int)(((const long long*)targets)[row]) : t32[row];
                size_t off = (size_t)row * C + tgti;
                float xt[4] = {__ldg(o0 + off), __ldg(o1 + off),
                               __ldg(o2 + off), __ldg(o3 + off)};

                const float invC = 1.0f / (float)C;
                float CE[4], KD[4];
#pragma unroll
                for (int j = 0; j < 4; j++) {
                    float lse1 = lg_(rr[j]);           // logsumexp(x),   M=0
                    float lses = lg_(rr[4 + j]);       // logsumexp(x/T)
                    float lset = lg_(rr[8 + j]);       // logsumexp(t/T)
                    CE[j] = lse1 - xt[j];
                    float S = rr[12 + j] / rr[8 + j];  // sum_c p_t*(m-x)
                    KD[j] = 9.0f * invC * ((0.2f / 3.f) * S + lses - lset);
                }

                float dd[10];
                int idx = 0;
#pragma unroll
                for (int j = 0; j < 4; j++)
#pragma unroll
                    for (int q = j; q < 4; q++) { dd[idx] = rr[16 + idx] - xt[j] * xt[q]; idx++; }
                float n0 = sqrtf(dd[0]), n1 = sqrtf(dd[4]), n2 = sqrtf(dd[7]), n3 = sqrtf(dd[9]);
                float dal = dd[1] / (n0 * n1) + dd[2] / (n0 * n2) + dd[3] / (n0 * n3)
                          + dd[5] / (n1 * n2) + dd[6] / (n1 * n3) + dd[8] / (n2 * n3);

                float irm = 0.f, mn = 3.402823466e38f;
#pragma unroll
                for (int j = 0; j < 4; j++) { irm += CE[j] + KD[j]; mn = fminf(mn, CE[j]); }
                stcg_(&g_L[row], irm + 0.7f * mn + 0.3f * dal);

                __threadfence();
                unsigned vd = atomicAdd(&g_done, 1u);
                s_last = (vd == (unsigned)(B - 1));
            }
            __syncthreads();

            if (s_last) {
                __threadfence();
                float a2 = 0.f;
                for (int i2 = tid; i2 < B; i2 += NTHREADS) a2 += ldcg_(&g_L[i2]);
                sf[tid] = a2;
                __syncthreads();
                for (int st = NTHREADS / 2; st > 0; st >>= 1) {
                    if (tid < st) sf[tid] += sf[tid + st];
                    __syncthreads();
                }
                if (tid == 0) {
                    out[0] = sf[0] / (float)B;
                    g_done = 0;  // reset for next replay
                }
            }
        }
    }
}

extern "C" void kernel_launch(void* const* d_in, const int* in_sizes, int n_in,
                              void* d_out, int out_size) {
    const float* o0 = (const float*)d_in[0];
    const float* o1 = (const float*)d_in[1];
    const float* o2 = (const float*)d_in[2];
    const float* o3 = (const float*)d_in[3];
    const void*  tg = d_in[4];
    const int B = in_sizes[4];
    const int C = in_sizes[0] / B;
    float* out = (float*)d_out;

    int dev = 0, nsm = 148;
    cudaGetDevice(&dev);
    cudaDeviceGetAttribute(&nsm, cudaDevAttrMultiProcessorCount, dev);

    const int C4    = C >> 2;
    const int IPR   = (C4 + NTHREADS - 1) / NTHREADS;
    const int UNITS = B * IPR;
    int grid = nsm * 4;
    if (grid > UNITS) grid = UNITS;
    const int UPC = (UNITS + grid - 1) / grid;

    aed_persist_kernel<<<grid, NTHREADS>>>(o0, o1, o2, o3, tg, out, C, B, UPC);
}